// round 13
// baseline (speedup 1.0000x reference)
#include <cuda_runtime.h>
#include <cuda_fp16.h>
#include <cstdint>

#define M_TOT 8192
#define N_TOT 4096
#define K_TOT 4096

#define BM 128
#define BN 128
#define BK 64
#define NT (K_TOT / BK)          // 64
#define STAGES 4

#define LDA 72                   // 64+8 halves; 144B = 9*16B odd -> conflict-free
#define LDB 136                  // 128+8 halves; 272B = 17*16B odd -> conflict-free
#define A_STAGE_BYTES (BM * LDA * 2)            // 18432
#define B_STAGE_BYTES (BK * LDB * 2)            // 17408
#define STAGE_BYTES (A_STAGE_BYTES + B_STAGE_BYTES)   // 35840
#define SMEM_TOTAL (STAGES * STAGE_BYTES)       // 143360 -> 1 CTA/SM

// Scratch (allocation-free rule: __device__ globals)
__device__ __half WH[(size_t)K_TOT * N_TOT];   // dequantized weight (K,N) n-major
__device__ __half XH[(size_t)M_TOT * K_TOT];   // fp16 activations (M,K) k-major

#define DQ_BLOCKS ((K_TOT / 8) * N_TOT / 256)          // 8192
#define XC_BLOCKS ((size_t)M_TOT * K_TOT / 4 / 256)    // 32768

// ---------------------------------------------------------------------------
// Fused prep: blocks [0, DQ_BLOCKS) dequant -> WH ; rest convert x -> XH
// ---------------------------------------------------------------------------
__global__ void prep_kernel(const float* __restrict__ x,
                            const int* __restrict__ qweight,
                            const int* __restrict__ qzeros,
                            const int* __restrict__ qscales,
                            const float* __restrict__ qs_zeros,
                            const float* __restrict__ qs_scales,
                            const int* __restrict__ g_idx) {
    if (blockIdx.x < DQ_BLOCKS) {
        int idx = blockIdx.x * 256 + threadIdx.x;      // over (K/8)*N
        int n  = idx % N_TOT;
        int kw = idx / N_TOT;

        int g = g_idx[kw * 8];                          // 8 | 32 -> same group
        int zw = qzeros[g * (N_TOT / 8) + (n >> 3)];
        int z  = ((zw >> ((n & 7) * 4)) & 0xF) + 1;
        float scale = ((float)qscales[g * N_TOT + n] - qs_zeros[g]) * qs_scales[g];
        int w = qweight[kw * N_TOT + n];

#pragma unroll
        for (int j = 0; j < 8; ++j) {
            int nib = (w >> (4 * j)) & 0xF;
            WH[(size_t)(kw * 8 + j) * N_TOT + n] =
                __float2half_rn((float)(nib - z) * scale);
        }
    } else {
        size_t i = (((size_t)blockIdx.x - DQ_BLOCKS) * 256 + threadIdx.x) * 4;
        float4 v = *(const float4*)(x + i);
        *(__half2*)(XH + i)     = __floats2half2_rn(v.x, v.y);
        *(__half2*)(XH + i + 2) = __floats2half2_rn(v.z, v.w);
    }
}

// ---------------------------------------------------------------------------
__device__ __forceinline__ uint32_t smem_u32(const void* p) {
    return (uint32_t)__cvta_generic_to_shared(p);
}
__device__ __forceinline__ void cp_async16(uint32_t s, const void* g) {
    asm volatile("cp.async.cg.shared.global [%0], [%1], 16;\n" :: "r"(s), "l"(g));
}
__device__ __forceinline__ void cp_commit() {
    asm volatile("cp.async.commit_group;\n" ::: "memory");
}
template <int Ngrp>
__device__ __forceinline__ void cp_wait() {
    asm volatile("cp.async.wait_group %0;\n" :: "n"(Ngrp) : "memory");
}

// ---------------------------------------------------------------------------
// fp16 GEMM, fp32 accum: out(M,N) = XH(M,K) @ WH(K,N)
// BM=BN=128, BK=64, 8 warps @ 64x32 warp tiles, 4-stage cp.async ring,
// register-double-buffered fragments (ldmatrix for ks+1 overlaps MMA of ks).
// ---------------------------------------------------------------------------
__global__ __launch_bounds__(256, 1)
void gemm_kernel(float* __restrict__ out) {
    extern __shared__ __align__(16) char sm[];
    const uint32_t smb = smem_u32(sm);

    const int tid  = threadIdx.x;
    const int warp = tid >> 5;
    const int lane = tid & 31;
    const int bm = blockIdx.y * BM;
    const int bn = blockIdx.x * BN;
    const int wm = (warp >> 2) * 64;    // 0 / 64
    const int wn = (warp & 3) * 32;     // 0 / 32 / 64 / 96

    float acc[4][4][4];
#pragma unroll
    for (int mi = 0; mi < 4; ++mi)
#pragma unroll
        for (int ni = 0; ni < 4; ++ni)
#pragma unroll
            for (int r = 0; r < 4; ++r) acc[mi][ni][r] = 0.f;

    // A: 128 rows x 8 chunks(16B); B: 64 rows x 16 chunks
    auto prefetch = [&](int s, int k0) {
        const uint32_t Ab = smb + s * STAGE_BYTES;
        const uint32_t Bb = Ab + A_STAGE_BYTES;
#pragma unroll
        for (int i = 0; i < 4; ++i) {
            int c = tid + i * 256;
            int row = c >> 3, col = (c & 7) * 8;
            cp_async16(Ab + row * (LDA * 2) + col * 2,
                       XH + (size_t)(bm + row) * K_TOT + k0 + col);
        }
#pragma unroll
        for (int i = 0; i < 4; ++i) {
            int c = tid + i * 256;
            int row = c >> 4, col = (c & 15) * 8;
            cp_async16(Bb + row * (LDB * 2) + col * 2,
                       WH + (size_t)(k0 + row) * N_TOT + bn + col);
        }
        cp_commit();
    };

    uint32_t a[2][4][4];
    uint32_t b[2][4][2];

    // frag load: parity p, stage bases, sub-step ks
    auto load_frags = [&](int p, uint32_t Ab, uint32_t Bb, int ks) {
#pragma unroll
        for (int mi = 0; mi < 4; ++mi) {
            uint32_t addr = Ab + (wm + mi * 16 + (lane & 15)) * (LDA * 2)
                          + (ks * 16 + (lane >> 4) * 8) * 2;
            asm volatile(
                "ldmatrix.sync.aligned.m8n8.x4.shared.b16 {%0,%1,%2,%3}, [%4];\n"
                : "=r"(a[p][mi][0]), "=r"(a[p][mi][1]),
                  "=r"(a[p][mi][2]), "=r"(a[p][mi][3])
                : "r"(addr));
        }
#pragma unroll
        for (int ni = 0; ni < 4; ++ni) {
            uint32_t addr = Bb + (ks * 16 + (lane & 15)) * (LDB * 2)
                          + (wn + ni * 8) * 2;
            asm volatile(
                "ldmatrix.sync.aligned.m8n8.x2.trans.shared.b16 {%0,%1}, [%2];\n"
                : "=r"(b[p][ni][0]), "=r"(b[p][ni][1])
                : "r"(addr));
        }
    };

    // Prologue: fill ring, ensure tiles 0 & 1 resident, preload frags (0, ks=0)
#pragma unroll
    for (int s = 0; s < STAGES; ++s) prefetch(s, s * BK);
    cp_wait<2>();                        // tiles 0,1 landed; 2,3 outstanding
    __syncthreads();
    load_frags(0, smb, smb + A_STAGE_BYTES, 0);

    for (int kt = 0; kt < NT; ++kt) {
        const int buf  = kt & 3;
        const int nbuf = (kt + 1) & 3;
        const uint32_t Ab  = smb + buf  * STAGE_BYTES, Bb  = Ab  + A_STAGE_BYTES;
        const uint32_t nAb = smb + nbuf * STAGE_BYTES, nBb = nAb + A_STAGE_BYTES;

#pragma unroll
        for (int ks = 0; ks < 4; ++ks) {
            const int p = ks & 1, q = p ^ 1;
            if (ks < 3) load_frags(q, Ab, Bb, ks + 1);
            else        load_frags(q, nAb, nBb, 0);   // tile kt+1 resident
#pragma unroll
            for (int mi = 0; mi < 4; ++mi)
#pragma unroll
                for (int ni = 0; ni < 4; ++ni) {
                    asm volatile(
                        "mma.sync.aligned.m16n8k16.row.col.f32.f16.f16.f32 "
                        "{%0,%1,%2,%3}, {%4,%5,%6,%7}, {%8,%9}, {%0,%1,%2,%3};\n"
                        : "+f"(acc[mi][ni][0]), "+f"(acc[mi][ni][1]),
                          "+f"(acc[mi][ni][2]), "+f"(acc[mi][ni][3])
                        : "r"(a[p][mi][0]), "r"(a[p][mi][1]),
                          "r"(a[p][mi][2]), "r"(a[p][mi][3]),
                          "r"(b[p][ni][0]), "r"(b[p][ni][1]));
                }
        }

        __syncthreads();                 // all reads of slot buf done
        if (kt + STAGES < NT) prefetch(buf, (kt + STAGES) * BK);
        else                  cp_commit();             // uniform group count
        cp_wait<2>();                    // tiles <= kt+2 resident
    }

    // Epilogue: m16n8 frag -> rows lane/4, lane/4+8; cols 2*(lane%4)+{0,1}
    const int r0 = lane >> 2;
    const int c0 = (lane & 3) * 2;
#pragma unroll
    for (int mi = 0; mi < 4; ++mi)
#pragma unroll
        for (int ni = 0; ni < 4; ++ni) {
            size_t base = (size_t)(bm + wm + mi * 16) * N_TOT + bn + wn + ni * 8;
            *(float2*)&out[base + (size_t)r0 * N_TOT + c0] =
                make_float2(acc[mi][ni][0], acc[mi][ni][1]);
            *(float2*)&out[base + (size_t)(r0 + 8) * N_TOT + c0] =
                make_float2(acc[mi][ni][2], acc[mi][ni][3]);
        }
}

// ---------------------------------------------------------------------------
extern "C" void kernel_launch(void* const* d_in, const int* in_sizes, int n_in,
                              void* d_out, int out_size) {
    const float* x        = (const float*)d_in[0];
    const int*   qweight  = (const int*)d_in[1];
    const int*   qzeros   = (const int*)d_in[2];
    const int*   qscales  = (const int*)d_in[3];
    const float* qsz      = (const float*)d_in[4];
    const float* qss      = (const float*)d_in[5];
    const int*   g_idx    = (const int*)d_in[6];
    float*       out      = (float*)d_out;

    {
        unsigned grid = (unsigned)(DQ_BLOCKS + XC_BLOCKS);   // 40960
        prep_kernel<<<grid, 256>>>(x, qweight, qzeros, qscales, qsz, qss, g_idx);
    }
    {
        cudaFuncSetAttribute(gemm_kernel,
                             cudaFuncAttributeMaxDynamicSharedMemorySize, SMEM_TOTAL);
        dim3 grid(N_TOT / BN, M_TOT / BM);    // (32, 64)
        gemm_kernel<<<grid, 256, SMEM_TOTAL>>>(out);
    }
}

// round 14
// speedup vs baseline: 1.4758x; 1.4758x over previous
#include <cuda_runtime.h>
#include <cuda_fp16.h>
#include <cstdint>

#define M_TOT 8192
#define N_TOT 4096
#define K_TOT 4096

#define BM 128
#define BN 256
#define BK 64
#define NT (K_TOT / BK)          // 64
#define STAGES 4

#define LDA 72                   // 64+8 halves; 144B = 9*16B odd -> conflict-free
#define LDB 264                  // 256+8 halves; 528B = 33*16B odd -> conflict-free
#define A_STAGE_BYTES (BM * LDA * 2)            // 18432
#define B_STAGE_BYTES (BK * LDB * 2)            // 33792
#define STAGE_BYTES (A_STAGE_BYTES + B_STAGE_BYTES)   // 52224
#define SMEM_TOTAL (STAGES * STAGE_BYTES)       // 208896 (<227KB), 1 CTA/SM

// Scratch (allocation-free rule: __device__ globals)
__device__ __half WH[(size_t)K_TOT * N_TOT];   // dequantized weight (K,N) n-major
__device__ __half XH[(size_t)M_TOT * K_TOT];   // fp16 activations (M,K) k-major

#define DQ_BLOCKS ((K_TOT / 8) * N_TOT / 256)          // 8192
#define XC_BLOCKS ((size_t)M_TOT * K_TOT / 4 / 256)    // 32768

// ---------------------------------------------------------------------------
// Fused prep: blocks [0, DQ_BLOCKS) dequant -> WH ; rest convert x -> XH
// ---------------------------------------------------------------------------
__global__ void prep_kernel(const float* __restrict__ x,
                            const int* __restrict__ qweight,
                            const int* __restrict__ qzeros,
                            const int* __restrict__ qscales,
                            const float* __restrict__ qs_zeros,
                            const float* __restrict__ qs_scales,
                            const int* __restrict__ g_idx) {
    if (blockIdx.x < DQ_BLOCKS) {
        int idx = blockIdx.x * 256 + threadIdx.x;      // over (K/8)*N
        int n  = idx % N_TOT;
        int kw = idx / N_TOT;

        int g = g_idx[kw * 8];                          // 8 | 32 -> same group
        int zw = qzeros[g * (N_TOT / 8) + (n >> 3)];
        int z  = ((zw >> ((n & 7) * 4)) & 0xF) + 1;
        float scale = ((float)qscales[g * N_TOT + n] - qs_zeros[g]) * qs_scales[g];
        int w = qweight[kw * N_TOT + n];

#pragma unroll
        for (int j = 0; j < 8; ++j) {
            int nib = (w >> (4 * j)) & 0xF;
            WH[(size_t)(kw * 8 + j) * N_TOT + n] =
                __float2half_rn((float)(nib - z) * scale);
        }
    } else {
        size_t i = (((size_t)blockIdx.x - DQ_BLOCKS) * 256 + threadIdx.x) * 4;
        float4 v = *(const float4*)(x + i);
        *(__half2*)(XH + i)     = __floats2half2_rn(v.x, v.y);
        *(__half2*)(XH + i + 2) = __floats2half2_rn(v.z, v.w);
    }
}

// ---------------------------------------------------------------------------
__device__ __forceinline__ uint32_t smem_u32(const void* p) {
    return (uint32_t)__cvta_generic_to_shared(p);
}
__device__ __forceinline__ void cp_async16(uint32_t s, const void* g) {
    asm volatile("cp.async.cg.shared.global [%0], [%1], 16;\n" :: "r"(s), "l"(g));
}
__device__ __forceinline__ void cp_commit() {
    asm volatile("cp.async.commit_group;\n" ::: "memory");
}
template <int Ngrp>
__device__ __forceinline__ void cp_wait() {
    asm volatile("cp.async.wait_group %0;\n" :: "n"(Ngrp) : "memory");
}

// ---------------------------------------------------------------------------
// fp16 GEMM, fp32 accum: out(M,N) = XH(M,K) @ WH(K,N)
// BM=128 BN=256 BK=64, 512 threads (16 warps @ 64x32 tiles), 4-stage ring,
// register-double-buffered fragments, ONE barrier per k-tile.
// ---------------------------------------------------------------------------
__global__ __launch_bounds__(512, 1)
void gemm_kernel(float* __restrict__ out) {
    extern __shared__ __align__(16) char sm[];
    const uint32_t smb = smem_u32(sm);

    const int tid  = threadIdx.x;
    const int warp = tid >> 5;
    const int lane = tid & 31;
    const int bm = blockIdx.y * BM;
    const int bn = blockIdx.x * BN;
    const int wm = (warp >> 3) * 64;    // 0 / 64
    const int wn = (warp & 7) * 32;     // 0..224 step 32

    float acc[4][4][4];
#pragma unroll
    for (int mi = 0; mi < 4; ++mi)
#pragma unroll
        for (int ni = 0; ni < 4; ++ni)
#pragma unroll
            for (int r = 0; r < 4; ++r) acc[mi][ni][r] = 0.f;

    // A: 128 rows x 8 chunks(16B) = 1024; B: 64 rows x 32 chunks = 2048
    const __half* gA = XH + (size_t)(bm + (tid >> 3)) * K_TOT + (tid & 7) * 8;
    const __half* gB = WH + (size_t)(tid >> 5) * N_TOT + bn + (tid & 31) * 8;
    auto prefetch = [&](int s, int k0) {
        const uint32_t Ab = smb + s * STAGE_BYTES;
        const uint32_t Bb = Ab + A_STAGE_BYTES;
#pragma unroll
        for (int i = 0; i < 2; ++i) {
            int c = tid + i * 512;
            int row = c >> 3, col = (c & 7) * 8;
            cp_async16(Ab + row * (LDA * 2) + col * 2,
                       gA + (size_t)(i * 64) * K_TOT + k0);
        }
#pragma unroll
        for (int i = 0; i < 4; ++i) {
            int c = tid + i * 512;
            int row = c >> 5;
            cp_async16(Bb + row * (LDB * 2) + (c & 31) * 16,
                       gB + (size_t)(k0 + i * 16) * N_TOT);
        }
        cp_commit();
    };

    uint32_t a[2][4][4];
    uint32_t b[2][4][2];

    auto load_frags = [&](int p, uint32_t Ab, uint32_t Bb, int ks) {
#pragma unroll
        for (int mi = 0; mi < 4; ++mi) {
            uint32_t addr = Ab + (wm + mi * 16 + (lane & 15)) * (LDA * 2)
                          + (ks * 16 + (lane >> 4) * 8) * 2;
            asm volatile(
                "ldmatrix.sync.aligned.m8n8.x4.shared.b16 {%0,%1,%2,%3}, [%4];\n"
                : "=r"(a[p][mi][0]), "=r"(a[p][mi][1]),
                  "=r"(a[p][mi][2]), "=r"(a[p][mi][3])
                : "r"(addr));
        }
#pragma unroll
        for (int ni = 0; ni < 4; ++ni) {
            uint32_t addr = Bb + (ks * 16 + (lane & 15)) * (LDB * 2)
                          + (wn + ni * 8) * 2;
            asm volatile(
                "ldmatrix.sync.aligned.m8n8.x2.trans.shared.b16 {%0,%1}, [%2];\n"
                : "=r"(b[p][ni][0]), "=r"(b[p][ni][1])
                : "r"(addr));
        }
    };

    // Prologue: fill ring; tiles 0,1 resident; preload frags for (tile0, ks0)
#pragma unroll
    for (int s = 0; s < STAGES; ++s) prefetch(s, s * BK);
    cp_wait<2>();
    __syncthreads();
    load_frags(0, smb, smb + A_STAGE_BYTES, 0);

    for (int kt = 0; kt < NT; ++kt) {
        const int buf  = kt & 3;
        const int nbuf = (kt + 1) & 3;
        const uint32_t Ab  = smb + buf  * STAGE_BYTES, Bb  = Ab  + A_STAGE_BYTES;
        const uint32_t nAb = smb + nbuf * STAGE_BYTES, nBb = nAb + A_STAGE_BYTES;

#pragma unroll
        for (int ks = 0; ks < 4; ++ks) {
            const int p = ks & 1, q = p ^ 1;
            if (ks < 3) load_frags(q, Ab, Bb, ks + 1);
            else        load_frags(q, nAb, nBb, 0);   // tile kt+1 resident
#pragma unroll
            for (int mi = 0; mi < 4; ++mi)
#pragma unroll
                for (int ni = 0; ni < 4; ++ni) {
                    asm volatile(
                        "mma.sync.aligned.m16n8k16.row.col.f32.f16.f16.f32 "
                        "{%0,%1,%2,%3}, {%4,%5,%6,%7}, {%8,%9}, {%0,%1,%2,%3};\n"
                        : "+f"(acc[mi][ni][0]), "+f"(acc[mi][ni][1]),
                          "+f"(acc[mi][ni][2]), "+f"(acc[mi][ni][3])
                        : "r"(a[p][mi][0]), "r"(a[p][mi][1]),
                          "r"(a[p][mi][2]), "r"(a[p][mi][3]),
                          "r"(b[p][ni][0]), "r"(b[p][ni][1]));
                }
        }

        // One barrier: every warp finished READING tile kt's slot (its last
        // reads happened at ks<=2; ks=3 reads slot kt+1). Safe to overwrite.
        __syncthreads();
        if (kt + STAGES < NT) prefetch(buf, (kt + STAGES) * BK);
        else                  cp_commit();             // uniform group count
        cp_wait<2>();        // tile kt+2 resident -> invariant for next iter
    }

    // Epilogue: m16n8 frag -> rows lane/4, lane/4+8; cols 2*(lane%4)+{0,1}
    const int r0 = lane >> 2;
    const int c0 = (lane & 3) * 2;
#pragma unroll
    for (int mi = 0; mi < 4; ++mi)
#pragma unroll
        for (int ni = 0; ni < 4; ++ni) {
            size_t base = (size_t)(bm + wm + mi * 16) * N_TOT + bn + wn + ni * 8;
            *(float2*)&out[base + (size_t)r0 * N_TOT + c0] =
                make_float2(acc[mi][ni][0], acc[mi][ni][1]);
            *(float2*)&out[base + (size_t)(r0 + 8) * N_TOT + c0] =
                make_float2(acc[mi][ni][2], acc[mi][ni][3]);
        }
}

// ---------------------------------------------------------------------------
extern "C" void kernel_launch(void* const* d_in, const int* in_sizes, int n_in,
                              void* d_out, int out_size) {
    const float* x        = (const float*)d_in[0];
    const int*   qweight  = (const int*)d_in[1];
    const int*   qzeros   = (const int*)d_in[2];
    const int*   qscales  = (const int*)d_in[3];
    const float* qsz      = (const float*)d_in[4];
    const float* qss      = (const float*)d_in[5];
    const int*   g_idx    = (const int*)d_in[6];
    float*       out      = (float*)d_out;

    {
        unsigned grid = (unsigned)(DQ_BLOCKS + XC_BLOCKS);   // 40960
        prep_kernel<<<grid, 256>>>(x, qweight, qzeros, qscales, qsz, qss, g_idx);
    }
    {
        cudaFuncSetAttribute(gemm_kernel,
                             cudaFuncAttributeMaxDynamicSharedMemorySize, SMEM_TOTAL);
        dim3 grid(N_TOT / BN, M_TOT / BM);    // (16, 64)
        gemm_kernel<<<grid, 512, SMEM_TOTAL>>>(out);
    }
}

// round 15
// speedup vs baseline: 1.6820x; 1.1397x over previous
#include <cuda_runtime.h>
#include <cuda_fp16.h>
#include <cstdint>

#define M_TOT 8192
#define N_TOT 4096
#define K_TOT 4096

#define BM 128
#define BN 256
#define BK 64
#define NT (K_TOT / BK)          // 64
#define STAGES 4

#define LDA 72                   // 64+8 halves; 144B = 9*16B odd -> conflict-free
#define LDB 264                  // 256+8 halves; 528B = 33*16B odd -> conflict-free
#define A_STAGE_BYTES (BM * LDA * 2)            // 18432
#define B_STAGE_BYTES (BK * LDB * 2)            // 33792
#define STAGE_BYTES (A_STAGE_BYTES + B_STAGE_BYTES)   // 52224
#define SMEM_TOTAL (STAGES * STAGE_BYTES)       // 208896 (<227KB), 1 CTA/SM

// Scratch (allocation-free rule: __device__ globals)
__device__ __half WH[(size_t)K_TOT * N_TOT];   // dequantized weight (K,N) n-major
__device__ __half XH[(size_t)M_TOT * K_TOT];   // fp16 activations (M,K) k-major

#define DQ_BLOCKS ((K_TOT / 8) * N_TOT / 256)          // 8192
#define XC_BLOCKS ((size_t)M_TOT * K_TOT / 4 / 256)    // 32768

// ---------------------------------------------------------------------------
// Fused prep: blocks [0, DQ_BLOCKS) dequant -> WH ; rest convert x -> XH
// ---------------------------------------------------------------------------
__global__ void prep_kernel(const float* __restrict__ x,
                            const int* __restrict__ qweight,
                            const int* __restrict__ qzeros,
                            const int* __restrict__ qscales,
                            const float* __restrict__ qs_zeros,
                            const float* __restrict__ qs_scales,
                            const int* __restrict__ g_idx) {
    if (blockIdx.x < DQ_BLOCKS) {
        int idx = blockIdx.x * 256 + threadIdx.x;      // over (K/8)*N
        int n  = idx % N_TOT;
        int kw = idx / N_TOT;

        int g = g_idx[kw * 8];                          // 8 | 32 -> same group
        int zw = qzeros[g * (N_TOT / 8) + (n >> 3)];
        int z  = ((zw >> ((n & 7) * 4)) & 0xF) + 1;
        float scale = ((float)qscales[g * N_TOT + n] - qs_zeros[g]) * qs_scales[g];
        int w = qweight[kw * N_TOT + n];

#pragma unroll
        for (int j = 0; j < 8; ++j) {
            int nib = (w >> (4 * j)) & 0xF;
            WH[(size_t)(kw * 8 + j) * N_TOT + n] =
                __float2half_rn((float)(nib - z) * scale);
        }
    } else {
        size_t i = (((size_t)blockIdx.x - DQ_BLOCKS) * 256 + threadIdx.x) * 4;
        float4 v = *(const float4*)(x + i);
        *(__half2*)(XH + i)     = __floats2half2_rn(v.x, v.y);
        *(__half2*)(XH + i + 2) = __floats2half2_rn(v.z, v.w);
    }
}

// ---------------------------------------------------------------------------
__device__ __forceinline__ uint32_t smem_u32(const void* p) {
    return (uint32_t)__cvta_generic_to_shared(p);
}
__device__ __forceinline__ void cp_async16(uint32_t s, const void* g) {
    asm volatile("cp.async.cg.shared.global [%0], [%1], 16;\n" :: "r"(s), "l"(g));
}
__device__ __forceinline__ void cp_commit() {
    asm volatile("cp.async.commit_group;\n" ::: "memory");
}
template <int Ngrp>
__device__ __forceinline__ void cp_wait() {
    asm volatile("cp.async.wait_group %0;\n" :: "n"(Ngrp) : "memory");
}

// ---------------------------------------------------------------------------
// fp16 GEMM, fp32 accum: out(M,N) = XH(M,K) @ WH(K,N)
// BM=128 BN=256 BK=64, 512 threads (16 warps @ 64x32 tiles), 4-stage ring,
// frag double-buffering, cp.async SPREAD across ks sub-steps, x4 B-ldmatrix.
// ---------------------------------------------------------------------------
__global__ __launch_bounds__(512, 1)
void gemm_kernel(float* __restrict__ out) {
    extern __shared__ __align__(16) char sm[];
    const uint32_t smb = smem_u32(sm);

    const int tid  = threadIdx.x;
    const int warp = tid >> 5;
    const int lane = tid & 31;
    const int bm = blockIdx.y * BM;
    const int bn = blockIdx.x * BN;
    const int wm = (warp >> 3) * 64;    // 0 / 64
    const int wn = (warp & 7) * 32;     // 0..224 step 32

    float acc[4][4][4];
#pragma unroll
    for (int mi = 0; mi < 4; ++mi)
#pragma unroll
        for (int ni = 0; ni < 4; ++ni)
#pragma unroll
            for (int r = 0; r < 4; ++r) acc[mi][ni][r] = 0.f;

    // global src pointers (per-thread fixed lanes)
    const __half* gA = XH + (size_t)(bm + (tid >> 3)) * K_TOT + (tid & 7) * 8;
    const __half* gB = WH + (size_t)(tid >> 5) * N_TOT + bn + (tid & 31) * 8;

    // A: chunk i in {0,1}; B: chunk i in {0..3}
    auto pf_a = [&](int s, int k0, int i) {
        const uint32_t Ab = smb + s * STAGE_BYTES;
        int c = tid + i * 512;
        int row = c >> 3, col = (c & 7) * 8;
        cp_async16(Ab + row * (LDA * 2) + col * 2,
                   gA + (size_t)(i * 64) * K_TOT + k0);
    };
    auto pf_b = [&](int s, int k0, int i) {
        const uint32_t Bb = smb + s * STAGE_BYTES + A_STAGE_BYTES;
        int c = tid + i * 512;
        int row = c >> 5;
        cp_async16(Bb + row * (LDB * 2) + (c & 31) * 16,
                   gB + (size_t)(k0 + i * 16) * N_TOT);
    };
    auto prefetch_full = [&](int s, int k0) {
        pf_a(s, k0, 0); pf_a(s, k0, 1);
#pragma unroll
        for (int i = 0; i < 4; ++i) pf_b(s, k0, i);
        cp_commit();
    };

    uint32_t a[2][4][4];
    uint32_t b[2][4][2];

    auto load_frags = [&](int p, uint32_t Ab, uint32_t Bb, int ks) {
#pragma unroll
        for (int mi = 0; mi < 4; ++mi) {
            uint32_t addr = Ab + (wm + mi * 16 + (lane & 15)) * (LDA * 2)
                          + (ks * 16 + (lane >> 4) * 8) * 2;
            asm volatile(
                "ldmatrix.sync.aligned.m8n8.x4.shared.b16 {%0,%1,%2,%3}, [%4];\n"
                : "=r"(a[p][mi][0]), "=r"(a[p][mi][1]),
                  "=r"(a[p][mi][2]), "=r"(a[p][mi][3])
                : "r"(addr));
        }
        // B: x4.trans loads two adjacent n8 column-tiles per op
#pragma unroll
        for (int ni = 0; ni < 4; ni += 2) {
            uint32_t addr = Bb + (ks * 16 + (lane & 15)) * (LDB * 2)
                          + (wn + ni * 8 + (lane >> 4) * 8) * 2;
            asm volatile(
                "ldmatrix.sync.aligned.m8n8.x4.trans.shared.b16 {%0,%1,%2,%3}, [%4];\n"
                : "=r"(b[p][ni][0]), "=r"(b[p][ni][1]),
                  "=r"(b[p][ni + 1][0]), "=r"(b[p][ni + 1][1])
                : "r"(addr));
        }
    };

    // Prologue: prefetch tiles 0..2; tiles 0,1 resident; preload (tile0, ks0)
#pragma unroll
    for (int s = 0; s < 3; ++s) prefetch_full(s, s * BK);
    cp_wait<1>();                       // tiles 0,1 landed (tile 2 may be in flight)
    __syncthreads();
    load_frags(0, smb, smb + A_STAGE_BYTES, 0);

    for (int kt = 0; kt < NT; ++kt) {
        const int buf  = kt & 3;
        const int nbuf = (kt + 1) & 3;
        const uint32_t Ab  = smb + buf  * STAGE_BYTES, Bb  = Ab  + A_STAGE_BYTES;
        const uint32_t nAb = smb + nbuf * STAGE_BYTES, nBb = nAb + A_STAGE_BYTES;
        const int  pslot = (kt + 3) & 3;             // holds tile kt-1, freed by
        const int  pk    = (kt + 3) * BK;            // barrier at end of kt-1
        const bool pfon  = (kt + 3) < NT;

#pragma unroll
        for (int ks = 0; ks < 4; ++ks) {
            const int p = ks & 1, q = p ^ 1;
            if (ks < 3) load_frags(q, Ab, Bb, ks + 1);
            else        load_frags(q, nAb, nBb, 0);  // tile kt+1 resident
            // spread prefetch of tile kt+3: 2 A-chunks at ks0, one B-chunk each ks
            if (pfon) {
                if (ks == 0) { pf_a(pslot, pk, 0); pf_a(pslot, pk, 1); pf_b(pslot, pk, 0); }
                else         { pf_b(pslot, pk, ks); }
            }
#pragma unroll
            for (int mi = 0; mi < 4; ++mi)
#pragma unroll
                for (int ni = 0; ni < 4; ++ni) {
                    asm volatile(
                        "mma.sync.aligned.m16n8k16.row.col.f32.f16.f16.f32 "
                        "{%0,%1,%2,%3}, {%4,%5,%6,%7}, {%8,%9}, {%0,%1,%2,%3};\n"
                        : "+f"(acc[mi][ni][0]), "+f"(acc[mi][ni][1]),
                          "+f"(acc[mi][ni][2]), "+f"(acc[mi][ni][3])
                        : "r"(a[p][mi][0]), "r"(a[p][mi][1]),
                          "r"(a[p][mi][2]), "r"(a[p][mi][3]),
                          "r"(b[p][ni][0]), "r"(b[p][ni][1]));
                }
        }

        cp_commit();                    // close group for tile kt+3 (maybe empty)
        __syncthreads();                // all reads of slot buf done; pslot reuse ok
        cp_wait<1>();                   // tiles <= kt+2 landed -> next-iter invariant
    }

    // Epilogue: m16n8 frag -> rows lane/4, lane/4+8; cols 2*(lane%4)+{0,1}
    const int r0 = lane >> 2;
    const int c0 = (lane & 3) * 2;
#pragma unroll
    for (int mi = 0; mi < 4; ++mi)
#pragma unroll
        for (int ni = 0; ni < 4; ++ni) {
            size_t base = (size_t)(bm + wm + mi * 16) * N_TOT + bn + wn + ni * 8;
            *(float2*)&out[base + (size_t)r0 * N_TOT + c0] =
                make_float2(acc[mi][ni][0], acc[mi][ni][1]);
            *(float2*)&out[base + (size_t)(r0 + 8) * N_TOT + c0] =
                make_float2(acc[mi][ni][2], acc[mi][ni][3]);
        }
}

// ---------------------------------------------------------------------------
extern "C" void kernel_launch(void* const* d_in, const int* in_sizes, int n_in,
                              void* d_out, int out_size) {
    const float* x        = (const float*)d_in[0];
    const int*   qweight  = (const int*)d_in[1];
    const int*   qzeros   = (const int*)d_in[2];
    const int*   qscales  = (const int*)d_in[3];
    const float* qsz      = (const float*)d_in[4];
    const float* qss      = (const float*)d_in[5];
    const int*   g_idx    = (const int*)d_in[6];
    float*       out      = (float*)d_out;

    {
        unsigned grid = (unsigned)(DQ_BLOCKS + XC_BLOCKS);   // 40960
        prep_kernel<<<grid, 256>>>(x, qweight, qzeros, qscales, qsz, qss, g_idx);
    }
    {
        cudaFuncSetAttribute(gemm_kernel,
                             cudaFuncAttributeMaxDynamicSharedMemorySize, SMEM_TOTAL);
        dim3 grid(N_TOT / BN, M_TOT / BM);    // (16, 64)
        gemm_kernel<<<grid, 512, SMEM_TOTAL>>>(out);
    }
}